// round 5
// baseline (speedup 1.0000x reference)
#include <cuda_runtime.h>

// Relativistic charged-particle Lagrangian dynamics.
// H (J_uu) is reconstructed to match the reference's JAX/XLA f32 bits:
//   - tanh: XLA GPU f32 rational approximation (not libdevice tanhf)
//   - x@W.T / x@V.T: cublas-style ascending-k fma chains
//   - H[i][j] = (0.1*A_j)*A_i   (0.1 binds to the jacfwd tangent index)
//   - H[i][i] = ((0.1*A_i)*A_i + (0.2*x_i)*x_i) + eta_i   (XLA const-folded)
//   - explicit __fmul_rn/__fadd_rn (XLA fusions emit uncontracted mul/add)
// The 4x4 solve is exact (accurate minors, double-single determinant,
// compensated iterative refinement), so the only my-vs-ref difference is H/f
// input bits. Rows near the jnp.linalg.pinv cutoff are compacted and
// re-solved with an fp64 Jacobi eigendecomposition + eigenvalue zeroing.

#define RCOND 4.7683716e-6f   /* 10 * 4 * eps(f32): jnp pinv default */
#define MAX_SLOW 262144

__device__ unsigned int g_slow_count;
__device__ int g_slow_idx[MAX_SLOW];

// ---------- XLA GPU f32 tanh (elemental_ir_emitter EmitTanh) ----------
__device__ __forceinline__ float xla_tanh(float x) {
    float ax = fabsf(x);
    float xc = fminf(fmaxf(x, -7.90531110763549805f), 7.90531110763549805f);
    float x2 = __fmul_rn(xc, xc);
    float np = -2.76076847742355e-16f;
    np = __fmaf_rn(np, x2, 2.00018790482477e-13f);
    np = __fmaf_rn(np, x2, -8.60467152213735e-11f);
    np = __fmaf_rn(np, x2, 5.12229709037114e-08f);
    np = __fmaf_rn(np, x2, 1.48572235717979e-05f);
    np = __fmaf_rn(np, x2, 6.37261928875436e-04f);
    np = __fmaf_rn(np, x2, 4.89352455891786e-03f);
    float num = __fmul_rn(xc, np);
    float dp = 1.19825839466702e-06f;
    dp = __fmaf_rn(dp, x2, 1.18534705686654e-04f);
    dp = __fmaf_rn(dp, x2, 2.26843463243900e-03f);
    dp = __fmaf_rn(dp, x2, 4.89352518554385e-03f);
    float r = __fdiv_rn(num, dp);
    return (ax < 0.0004f) ? x : r;
}

// ---------- double-single helpers ----------
__device__ __forceinline__ void two_sum(float a, float b, float& s, float& e) {
    s = a + b;
    float bb = s - a;
    e = (a - (s - bb)) + (b - bb);
}
__device__ __forceinline__ void two_prod(float a, float b, float& p, float& e) {
    p = a * b;
    e = fmaf(a, b, -p);
}
__device__ __forceinline__ float dif2(float p0, float p1, float q0, float q1) {
    float w = q0 * q1;
    float e = fmaf(q0, q1, -w);
    float r = fmaf(p0, p1, -w);
    return r - e;
}

// ---------- shared physics: J_uu (m) and force for one row ----------
__device__ __forceinline__ void compute_mf(const float4* __restrict__ y,
                                           const float*  __restrict__ Wg,
                                           const float*  __restrict__ Vg,
                                           int b, float m[4][4], float force[4])
{
    const float eta[4] = {1.f, -1.f, -1.f, -1.f};
    float4 xv = y[2 * b];
    float4 uv = y[2 * b + 1];
    float x[4] = {xv.x, xv.y, xv.z, xv.w};
    float u[4] = {uv.x, uv.y, uv.z, uv.w};

    // A_i = xla_tanh(W[i,:].x) + V[i,:].x  (cublas ascending-k fma chains)
    float A[4], dk[4];
#pragma unroll
    for (int i = 0; i < 4; i++) {
        float wx = __fmul_rn(Wg[i*4+0], x[0]);
        wx = __fmaf_rn(Wg[i*4+1], x[1], wx);
        wx = __fmaf_rn(Wg[i*4+2], x[2], wx);
        wx = __fmaf_rn(Wg[i*4+3], x[3], wx);
        float vx = __fmul_rn(Vg[i*4+0], x[0]);
        vx = __fmaf_rn(Vg[i*4+1], x[1], vx);
        vx = __fmaf_rn(Vg[i*4+2], x[2], vx);
        vx = __fmaf_rn(Vg[i*4+3], x[3], vx);
        float t = xla_tanh(wx);
        A[i]  = __fadd_rn(t, vx);
        dk[i] = __fsub_rn(1.0f, __fmul_rn(t, t));   // tanh jvp: 1 - ans*ans
    }

    // ---- J_uu per autodiff graph (CRITICAL: bit-level layout) ----
    // oA[j] = 0.1*A_j ; H[i][j] = oA[j]*A_i ; diag: ((oA[i]*A_i + (0.2x_i)*x_i) + eta_i)
    float oA[4];
#pragma unroll
    for (int j = 0; j < 4; j++)
        oA[j] = __fmul_rn(0.1f, A[j]);
#pragma unroll
    for (int i = 0; i < 4; i++) {
#pragma unroll
        for (int j = 0; j < 4; j++)
            m[i][j] = __fmul_rn(oA[j], A[i]);
        float xu2 = __fmul_rn(__fmul_rn(0.2f, x[i]), x[i]);
        m[i][i] = __fadd_rn(__fadd_rn(m[i][i], xu2), eta[i]);
    }

    // ---- force (rounding here is NOT amplified; any faithful order works) ----
    // dA_dx[j][k] = W[k][j]*dk_k + V[k][j]
    float G[4][4];
#pragma unroll
    for (int k = 0; k < 4; k++)
#pragma unroll
        for (int j = 0; j < 4; j++)
            G[j][k] = __fadd_rn(__fmul_rn(Wg[k*4+j], dk[k]), Vg[k*4+j]);

    // s4 = sum(u*A) left-assoc
    float s4 = __fadd_rn(__fadd_rn(__fadd_rn(
                   __fmul_rn(u[0], A[0]), __fmul_rn(u[1], A[1])),
                   __fmul_rn(u[2], A[2])), __fmul_rn(u[3], A[3]));
    float c01 = __fmul_rn(0.1f, s4);

    // dL_dx_i = (0.2*(x_i*u_i))*u_i
    float dLdx[4];
#pragma unroll
    for (int i = 0; i < 4; i++)
        dLdx[i] = __fmul_rn(__fmul_rn(0.2f, __fmul_rn(x[i], u[i])), u[i]);

    // dL_dA_k = (0.1*s4)*u_k + 0.5*(eta_k*u_k)
    float dLdA[4];
#pragma unroll
    for (int k = 0; k < 4; k++)
        dLdA[k] = __fadd_rn(__fmul_rn(c01, u[k]),
                            __fmul_rn(0.5f, __fmul_rn(eta[k], u[k])));

    // e1_j = sum_k G[j][k]*dL_dA_k
    float e1[4];
#pragma unroll
    for (int j = 0; j < 4; j++) {
        float a = __fmul_rn(G[j][0], dLdA[0]);
        a = __fmaf_rn(G[j][1], dLdA[1], a);
        a = __fmaf_rn(G[j][2], dLdA[2], a);
        a = __fmaf_rn(G[j][3], dLdA[3], a);
        e1[j] = a;
    }

    // J_Au[k][mm] = (0.1*A_mm)*u_k + delta*(0.1*s4) + delta*(0.5*eta_k)
    float jau[4][4];
#pragma unroll
    for (int k = 0; k < 4; k++) {
#pragma unroll
        for (int mm = 0; mm < 4; mm++)
            jau[k][mm] = __fmul_rn(oA[mm], u[k]);
        jau[k][k] = __fadd_rn(__fadd_rn(jau[k][k], c01),
                              __fmul_rn(0.5f, eta[k]));
    }

    // S[i][mm] = J_xu[i][mm] + sum_k G[i][k]*J_Au[k][mm]
    // J_xu diag = (0.2*x_i)*u_i + 0.2*(x_i*u_i)
    float S[4][4];
#pragma unroll
    for (int i = 0; i < 4; i++) {
        float jxu = __fadd_rn(__fmul_rn(__fmul_rn(0.2f, x[i]), u[i]),
                              __fmul_rn(0.2f, __fmul_rn(x[i], u[i])));
#pragma unroll
        for (int mm = 0; mm < 4; mm++) {
            float a = __fmul_rn(G[i][0], jau[0][mm]);
            a = __fmaf_rn(G[i][1], jau[1][mm], a);
            a = __fmaf_rn(G[i][2], jau[2][mm], a);
            a = __fmaf_rn(G[i][3], jau[3][mm], a);
            S[i][mm] = (i == mm) ? __fadd_rn(jxu, a) : a;
        }
    }

    // force_j = (dL_dx_j + e1_j) - sum_i u_i*S[i][j]
#pragma unroll
    for (int j = 0; j < 4; j++) {
        float e2 = __fmul_rn(u[0], S[0][j]);
        e2 = __fmaf_rn(u[1], S[1][j], e2);
        e2 = __fmaf_rn(u[2], S[2][j], e2);
        e2 = __fmaf_rn(u[3], S[3][j], e2);
        force[j] = __fsub_rn(__fadd_rn(dLdx[j], e1[j]), e2);
    }
}

// ---------- kernel 0: reset slow-row counter ----------
__global__ void rcpl_reset() { g_slow_count = 0u; }

// ---------- kernel 1: fast path ----------
__global__ void __launch_bounds__(256)
rcpl_fast(const float4* __restrict__ y,
          const float*  __restrict__ Wg,
          const float*  __restrict__ Vg,
          float4* __restrict__ out,
          int B)
{
    int b = blockIdx.x * blockDim.x + threadIdx.x;
    if (b >= B) return;

    float m[4][4], f[4];
    compute_mf(y, Wg, Vg, b, m, f);

    // accurate 2x2 minors
    float s0 = dif2(m[0][0], m[1][1], m[1][0], m[0][1]);
    float s1 = dif2(m[0][0], m[1][2], m[1][0], m[0][2]);
    float s2 = dif2(m[0][0], m[1][3], m[1][0], m[0][3]);
    float s3 = dif2(m[0][1], m[1][2], m[1][1], m[0][2]);
    float s4 = dif2(m[0][1], m[1][3], m[1][1], m[0][3]);
    float s5 = dif2(m[0][2], m[1][3], m[1][2], m[0][3]);

    float c5 = dif2(m[2][2], m[3][3], m[3][2], m[2][3]);
    float c4 = dif2(m[2][1], m[3][3], m[3][1], m[2][3]);
    float c3 = dif2(m[2][1], m[3][2], m[3][1], m[2][2]);
    float c2 = dif2(m[2][0], m[3][3], m[3][0], m[2][3]);
    float c1 = dif2(m[2][0], m[3][2], m[3][0], m[2][2]);
    float c0 = dif2(m[2][0], m[3][1], m[3][0], m[2][1]);

    // determinant in double-single
    float hi, lo, p, e, t;
    two_prod(s0, c5, hi, lo);
    two_prod(-s1, c4, p, e); two_sum(hi, p, hi, t); lo += t + e;
    two_prod(s2, c3, p, e);  two_sum(hi, p, hi, t); lo += t + e;
    two_prod(s3, c2, p, e);  two_sum(hi, p, hi, t); lo += t + e;
    two_prod(-s4, c1, p, e); two_sum(hi, p, hi, t); lo += t + e;
    two_prod(s5, c0, p, e);  two_sum(hi, p, hi, t); lo += t + e;

    // route rows with lam_min near/below the pinv cutoff to the slow path
    float sF2 = 0.f;
#pragma unroll
    for (int i = 0; i < 4; i++)
#pragma unroll
        for (int j = 0; j < 4; j++)
            sF2 = fmaf(m[i][j], m[i][j], sF2);
    float thr = 4.0f * RCOND * sF2 * sF2;

    if (fabsf(hi + lo) < thr) {
        unsigned idx = atomicAdd(&g_slow_count, 1u);
        if (idx < MAX_SLOW) g_slow_idx[idx] = b;
    }

    float inv = 1.0f / hi;
    inv = fmaf(-lo, inv * inv, inv);

    float adj[4][4];
    adj[0][0] =  m[1][1]*c5 - m[1][2]*c4 + m[1][3]*c3;
    adj[0][1] = -m[0][1]*c5 + m[0][2]*c4 - m[0][3]*c3;
    adj[0][2] =  m[3][1]*s5 - m[3][2]*s4 + m[3][3]*s3;
    adj[0][3] = -m[2][1]*s5 + m[2][2]*s4 - m[2][3]*s3;
    adj[1][0] = -m[1][0]*c5 + m[1][2]*c2 - m[1][3]*c1;
    adj[1][1] =  m[0][0]*c5 - m[0][2]*c2 + m[0][3]*c1;
    adj[1][2] = -m[3][0]*s5 + m[3][2]*s2 - m[3][3]*s1;
    adj[1][3] =  m[2][0]*s5 - m[2][2]*s2 + m[2][3]*s1;
    adj[2][0] =  m[1][0]*c4 - m[1][1]*c2 + m[1][3]*c0;
    adj[2][1] = -m[0][0]*c4 + m[0][1]*c2 - m[0][3]*c0;
    adj[2][2] =  m[3][0]*s4 - m[3][1]*s2 + m[3][3]*s0;
    adj[2][3] = -m[2][0]*s4 + m[2][1]*s2 - m[2][3]*s0;
    adj[3][0] = -m[1][0]*c3 + m[1][1]*c1 - m[1][2]*c0;
    adj[3][1] =  m[0][0]*c3 - m[0][1]*c1 + m[0][2]*c0;
    adj[3][2] = -m[3][0]*s3 + m[3][1]*s1 - m[3][2]*s0;
    adj[3][3] =  m[2][0]*s3 - m[2][1]*s1 + m[2][2]*s0;

    float acc[4];
#pragma unroll
    for (int j = 0; j < 4; j++)
        acc[j] = (f[0]*adj[0][j] + f[1]*adj[1][j] + f[2]*adj[2][j] + f[3]*adj[3][j]) * inv;

    // iterative refinement x2 with compensated residual
#pragma unroll
    for (int it = 0; it < 2; it++) {
        float r[4];
#pragma unroll
        for (int i = 0; i < 4; i++) {
            float rh = f[i], rl = 0.f;
#pragma unroll
            for (int k = 0; k < 4; k++) {
                float ph, pe;
                two_prod(m[i][k], acc[k], ph, pe);
                float sh, se;
                two_sum(rh, -ph, sh, se);
                rh = sh;
                rl += se - pe;
            }
            r[i] = rh + rl;
        }
#pragma unroll
        for (int j = 0; j < 4; j++)
            acc[j] += (r[0]*adj[0][j] + r[1]*adj[1][j]
                     + r[2]*adj[2][j] + r[3]*adj[3][j]) * inv;
    }

    out[b] = make_float4(acc[0], acc[1], acc[2], acc[3]);
}

// ---------- kernel 2: slow path — fp64 Jacobi eigen + pinv cutoff ----------
__global__ void rcpl_slow(const float4* __restrict__ y,
                          const float*  __restrict__ Wg,
                          const float*  __restrict__ Vg,
                          float4* __restrict__ out)
{
    unsigned count = g_slow_count;
    if (count > MAX_SLOW) count = MAX_SLOW;

    for (unsigned i = blockIdx.x * blockDim.x + threadIdx.x; i < count;
         i += gridDim.x * blockDim.x)
    {
        int b = g_slow_idx[i];
        float mf[4][4], ff[4];
        compute_mf(y, Wg, Vg, b, mf, ff);

        double A[4][4], Q[4][4], fd[4];
#pragma unroll
        for (int r = 0; r < 4; r++) {
            fd[r] = (double)ff[r];
#pragma unroll
            for (int c = 0; c < 4; c++) {
                A[r][c] = (double)mf[r][c];
                Q[r][c] = (r == c) ? 1.0 : 0.0;
            }
        }

        for (int sweep = 0; sweep < 7; sweep++) {
#pragma unroll
            for (int pi = 0; pi < 3; pi++)
#pragma unroll
                for (int qi = pi + 1; qi < 4; qi++) {
                    double apq = A[pi][qi];
                    if (fabs(apq) < 1e-300) continue;
                    double theta = (A[qi][qi] - A[pi][pi]) / (2.0 * apq);
                    double tt = 1.0 / (fabs(theta) + sqrt(theta * theta + 1.0));
                    if (theta < 0.0) tt = -tt;
                    double c = 1.0 / sqrt(tt * tt + 1.0);
                    double s = tt * c;
#pragma unroll
                    for (int k = 0; k < 4; k++) {
                        double akp = A[k][pi], akq = A[k][qi];
                        A[k][pi] = c * akp - s * akq;
                        A[k][qi] = s * akp + c * akq;
                    }
#pragma unroll
                    for (int k = 0; k < 4; k++) {
                        double apk = A[pi][k], aqk = A[qi][k];
                        A[pi][k] = c * apk - s * aqk;
                        A[qi][k] = s * apk + c * aqk;
                    }
#pragma unroll
                    for (int k = 0; k < 4; k++) {
                        double qkp = Q[k][pi], qkq = Q[k][qi];
                        Q[k][pi] = c * qkp - s * qkq;
                        Q[k][qi] = s * qkp + c * qkq;
                    }
                }
        }

        double lam[4], smax = 0.0;
#pragma unroll
        for (int k = 0; k < 4; k++) {
            lam[k] = A[k][k];
            double a = fabs(lam[k]);
            if (a > smax) smax = a;
        }
        double cut = (double)RCOND * smax;

        double acc[4] = {0.0, 0.0, 0.0, 0.0};
#pragma unroll
        for (int k = 0; k < 4; k++) {
            if (fabs(lam[k]) > cut) {
                double w = (Q[0][k]*fd[0] + Q[1][k]*fd[1] +
                            Q[2][k]*fd[2] + Q[3][k]*fd[3]) / lam[k];
#pragma unroll
                for (int j = 0; j < 4; j++)
                    acc[j] += w * Q[j][k];
            }
        }

        out[b] = make_float4((float)acc[0], (float)acc[1],
                             (float)acc[2], (float)acc[3]);
    }
}

extern "C" void kernel_launch(void* const* d_in, const int* in_sizes, int n_in,
                              void* d_out, int out_size)
{
    const float* y = (const float*)d_in[0];
    const float* W = (const float*)d_in[1];
    const float* V = (const float*)d_in[2];
    int B = in_sizes[0] / 8;   // y is [B, 8]

    rcpl_reset<<<1, 1>>>();
    int threads = 256;
    int blocks = (B + threads - 1) / threads;
    rcpl_fast<<<blocks, threads>>>((const float4*)y, W, V, (float4*)d_out, B);
    rcpl_slow<<<64, 128>>>((const float4*)y, W, V, (float4*)d_out);
}

// round 6
// speedup vs baseline: 1.3744x; 1.3744x over previous
#include <cuda_runtime.h>

// Relativistic charged-particle Lagrangian dynamics.
// H (J_uu) matches the reference's JAX/XLA f32 bits exactly (XLA tanh
// rational approximation, cublas-style fma k-chains, autodiff association
// (0.1*A_j)*A_i, const-folded +eta). Force uses collapsed algebra (its
// rounding is not kappa-amplified). Solve = Cramer with accurate 2x2 minors
// + double-single determinant (proven bit-equal to the refined solve).
// Rows near the jnp.linalg.pinv cutoff -> fp64 Jacobi eigen + eigenvalue
// zeroing in a compacted second kernel, which also resets the row counter
// for the next graph replay (last-block-done pattern).

#define RCOND 4.7683716e-6f   /* 10 * 4 * eps(f32): jnp pinv default */
#define MAX_SLOW 262144

__device__ unsigned int g_slow_count = 0u;
__device__ unsigned int g_done_blocks = 0u;
__device__ int g_slow_idx[MAX_SLOW];

// ---------- XLA GPU f32 tanh ----------
__device__ __forceinline__ float xla_tanh(float x) {
    float ax = fabsf(x);
    float xc = fminf(fmaxf(x, -7.90531110763549805f), 7.90531110763549805f);
    float x2 = __fmul_rn(xc, xc);
    float np = -2.76076847742355e-16f;
    np = __fmaf_rn(np, x2, 2.00018790482477e-13f);
    np = __fmaf_rn(np, x2, -8.60467152213735e-11f);
    np = __fmaf_rn(np, x2, 5.12229709037114e-08f);
    np = __fmaf_rn(np, x2, 1.48572235717979e-05f);
    np = __fmaf_rn(np, x2, 6.37261928875436e-04f);
    np = __fmaf_rn(np, x2, 4.89352455891786e-03f);
    float num = __fmul_rn(xc, np);
    float dp = 1.19825839466702e-06f;
    dp = __fmaf_rn(dp, x2, 1.18534705686654e-04f);
    dp = __fmaf_rn(dp, x2, 2.26843463243900e-03f);
    dp = __fmaf_rn(dp, x2, 4.89352518554385e-03f);
    float r = __fdiv_rn(num, dp);
    return (ax < 0.0004f) ? x : r;
}

// ---------- double-single helpers ----------
__device__ __forceinline__ void two_sum(float a, float b, float& s, float& e) {
    s = a + b;
    float bb = s - a;
    e = (a - (s - bb)) + (b - bb);
}
__device__ __forceinline__ void two_prod(float a, float b, float& p, float& e) {
    p = a * b;
    e = fmaf(a, b, -p);
}
__device__ __forceinline__ float dif2(float p0, float p1, float q0, float q1) {
    float w = q0 * q1;
    float e = fmaf(q0, q1, -w);
    float r = fmaf(p0, p1, -w);
    return r - e;
}

// ---------- physics: J_uu (bit-exact vs reference) + force (compact) ----------
__device__ __forceinline__ void compute_mf(const float4* __restrict__ y,
                                           const float*  __restrict__ Wg,
                                           const float*  __restrict__ Vg,
                                           int b, float m[4][4], float force[4])
{
    const float eta[4] = {1.f, -1.f, -1.f, -1.f};
    float4 xv = y[2 * b];
    float4 uv = y[2 * b + 1];
    float x[4] = {xv.x, xv.y, xv.z, xv.w};
    float u[4] = {uv.x, uv.y, uv.z, uv.w};

    // A_i = xla_tanh(W[i,:].x) + V[i,:].x  (cublas ascending-k fma chains)
    float A[4], dk[4];
#pragma unroll
    for (int i = 0; i < 4; i++) {
        float wx = __fmul_rn(Wg[i*4+0], x[0]);
        wx = __fmaf_rn(Wg[i*4+1], x[1], wx);
        wx = __fmaf_rn(Wg[i*4+2], x[2], wx);
        wx = __fmaf_rn(Wg[i*4+3], x[3], wx);
        float vx = __fmul_rn(Vg[i*4+0], x[0]);
        vx = __fmaf_rn(Vg[i*4+1], x[1], vx);
        vx = __fmaf_rn(Vg[i*4+2], x[2], vx);
        vx = __fmaf_rn(Vg[i*4+3], x[3], vx);
        float t = xla_tanh(wx);
        A[i]  = __fadd_rn(t, vx);
        dk[i] = __fsub_rn(1.0f, __fmul_rn(t, t));
    }

    // ---- J_uu: BIT-CRITICAL layout (matches reference autodiff graph) ----
    float oA[4];
#pragma unroll
    for (int j = 0; j < 4; j++)
        oA[j] = __fmul_rn(0.1f, A[j]);
#pragma unroll
    for (int i = 0; i < 4; i++) {
#pragma unroll
        for (int j = 0; j < 4; j++)
            m[i][j] = __fmul_rn(oA[j], A[i]);
        float xx2 = __fmul_rn(__fmul_rn(0.2f, x[i]), x[i]);
        m[i][i] = __fadd_rn(__fadd_rn(m[i][i], xx2), eta[i]);
    }

    // ---- force: compact algebra (rounding not amplified) ----
    // G[j][k] = dA_k/dx_j = W[k][j]*dk_k + V[k][j]
    float G[4][4];
#pragma unroll
    for (int k = 0; k < 4; k++)
#pragma unroll
        for (int j = 0; j < 4; j++)
            G[j][k] = fmaf(Wg[k*4+j], dk[k], Vg[k*4+j]);

    float s = u[0]*A[0] + u[1]*A[1] + u[2]*A[2] + u[3]*A[3];
    float tbs = 0.1f * s;   // 2*beta*s

    float g[4], ge[4], h[4];
#pragma unroll
    for (int j = 0; j < 4; j++) {
        g[j]  = G[j][0]*u[0] + G[j][1]*u[1] + G[j][2]*u[2] + G[j][3]*u[3];
        ge[j] = G[j][0]*u[0] - G[j][1]*u[1] - G[j][2]*u[2] - G[j][3]*u[3];
        h[j]  = G[0][j]*u[0] + G[1][j]*u[1] + G[2][j]*u[2] + G[3][j]*u[3];
    }
    float p = h[0]*u[0] + h[1]*u[1] + h[2]*u[2] + h[3]*u[3];

#pragma unroll
    for (int j = 0; j < 4; j++) {
        force[j] = -0.2f * x[j] * u[j] * u[j]
                 + 0.5f * ge[j] + tbs * g[j]
                 - 0.5f * eta[j] * h[j] - tbs * h[j]
                 - 0.1f * p * A[j];
    }
}

// ---------- kernel 1: fast path ----------
__global__ void __launch_bounds__(256)
rcpl_fast(const float4* __restrict__ y,
          const float*  __restrict__ Wg,
          const float*  __restrict__ Vg,
          float4* __restrict__ out,
          int B)
{
    int b = blockIdx.x * blockDim.x + threadIdx.x;
    if (b >= B) return;

    float m[4][4], f[4];
    compute_mf(y, Wg, Vg, b, m, f);

    // accurate 2x2 minors
    float s0 = dif2(m[0][0], m[1][1], m[1][0], m[0][1]);
    float s1 = dif2(m[0][0], m[1][2], m[1][0], m[0][2]);
    float s2 = dif2(m[0][0], m[1][3], m[1][0], m[0][3]);
    float s3 = dif2(m[0][1], m[1][2], m[1][1], m[0][2]);
    float s4 = dif2(m[0][1], m[1][3], m[1][1], m[0][3]);
    float s5 = dif2(m[0][2], m[1][3], m[1][2], m[0][3]);

    float c5 = dif2(m[2][2], m[3][3], m[3][2], m[2][3]);
    float c4 = dif2(m[2][1], m[3][3], m[3][1], m[2][3]);
    float c3 = dif2(m[2][1], m[3][2], m[3][1], m[2][2]);
    float c2 = dif2(m[2][0], m[3][3], m[3][0], m[2][3]);
    float c1 = dif2(m[2][0], m[3][2], m[3][0], m[2][2]);
    float c0 = dif2(m[2][0], m[3][1], m[3][0], m[2][1]);

    // determinant in double-single
    float hi, lo, p, e, t;
    two_prod(s0, c5, hi, lo);
    two_prod(-s1, c4, p, e); two_sum(hi, p, hi, t); lo += t + e;
    two_prod(s2, c3, p, e);  two_sum(hi, p, hi, t); lo += t + e;
    two_prod(s3, c2, p, e);  two_sum(hi, p, hi, t); lo += t + e;
    two_prod(-s4, c1, p, e); two_sum(hi, p, hi, t); lo += t + e;
    two_prod(s5, c0, p, e);  two_sum(hi, p, hi, t); lo += t + e;

    // route rows with lam_min near/below the pinv cutoff to the slow path
    float sF2 = 0.f;
#pragma unroll
    for (int i = 0; i < 4; i++)
#pragma unroll
        for (int j = 0; j < 4; j++)
            sF2 = fmaf(m[i][j], m[i][j], sF2);
    float thr = 4.0f * RCOND * sF2 * sF2;

    if (fabsf(hi + lo) < thr) {
        unsigned idx = atomicAdd(&g_slow_count, 1u);
        if (idx < MAX_SLOW) g_slow_idx[idx] = b;
    }

    float inv = 1.0f / hi;
    inv = fmaf(-lo, inv * inv, inv);   // 1/(hi+lo)

    float adj[4][4];
    adj[0][0] =  m[1][1]*c5 - m[1][2]*c4 + m[1][3]*c3;
    adj[0][1] = -m[0][1]*c5 + m[0][2]*c4 - m[0][3]*c3;
    adj[0][2] =  m[3][1]*s5 - m[3][2]*s4 + m[3][3]*s3;
    adj[0][3] = -m[2][1]*s5 + m[2][2]*s4 - m[2][3]*s3;
    adj[1][0] = -m[1][0]*c5 + m[1][2]*c2 - m[1][3]*c1;
    adj[1][1] =  m[0][0]*c5 - m[0][2]*c2 + m[0][3]*c1;
    adj[1][2] = -m[3][0]*s5 + m[3][2]*s2 - m[3][3]*s1;
    adj[1][3] =  m[2][0]*s5 - m[2][2]*s2 + m[2][3]*s1;
    adj[2][0] =  m[1][0]*c4 - m[1][1]*c2 + m[1][3]*c0;
    adj[2][1] = -m[0][0]*c4 + m[0][1]*c2 - m[0][3]*c0;
    adj[2][2] =  m[3][0]*s4 - m[3][1]*s2 + m[3][3]*s0;
    adj[2][3] = -m[2][0]*s4 + m[2][1]*s2 - m[2][3]*s0;
    adj[3][0] = -m[1][0]*c3 + m[1][1]*c1 - m[1][2]*c0;
    adj[3][1] =  m[0][0]*c3 - m[0][1]*c1 + m[0][2]*c0;
    adj[3][2] = -m[3][0]*s3 + m[3][1]*s1 - m[3][2]*s0;
    adj[3][3] =  m[2][0]*s3 - m[2][1]*s1 + m[2][2]*s0;

    float a0 = (f[0]*adj[0][0] + f[1]*adj[1][0] + f[2]*adj[2][0] + f[3]*adj[3][0]) * inv;
    float a1 = (f[0]*adj[0][1] + f[1]*adj[1][1] + f[2]*adj[2][1] + f[3]*adj[3][1]) * inv;
    float a2 = (f[0]*adj[0][2] + f[1]*adj[1][2] + f[2]*adj[2][2] + f[3]*adj[3][2]) * inv;
    float a3 = (f[0]*adj[0][3] + f[1]*adj[1][3] + f[2]*adj[2][3] + f[3]*adj[3][3]) * inv;

    out[b] = make_float4(a0, a1, a2, a3);
}

// ---------- kernel 2: slow path — fp64 Jacobi eigen + pinv cutoff ----------
// Also resets g_slow_count at the end (last-finishing block) so the next
// graph replay starts from zero. g_slow_count is statically zero-initialized
// for the very first call.
__global__ void rcpl_slow(const float4* __restrict__ y,
                          const float*  __restrict__ Wg,
                          const float*  __restrict__ Vg,
                          float4* __restrict__ out)
{
    unsigned count = g_slow_count;
    if (count > MAX_SLOW) count = MAX_SLOW;

    for (unsigned i = blockIdx.x * blockDim.x + threadIdx.x; i < count;
         i += gridDim.x * blockDim.x)
    {
        int b = g_slow_idx[i];
        float mf[4][4], ff[4];
        compute_mf(y, Wg, Vg, b, mf, ff);

        double A[4][4], Q[4][4], fd[4];
#pragma unroll
        for (int r = 0; r < 4; r++) {
            fd[r] = (double)ff[r];
#pragma unroll
            for (int c = 0; c < 4; c++) {
                A[r][c] = (double)mf[r][c];
                Q[r][c] = (r == c) ? 1.0 : 0.0;
            }
        }

        // cyclic Jacobi, 5 sweeps (quadratic convergence; safe for 4x4)
        for (int sweep = 0; sweep < 5; sweep++) {
#pragma unroll
            for (int pi = 0; pi < 3; pi++)
#pragma unroll
                for (int qi = pi + 1; qi < 4; qi++) {
                    double apq = A[pi][qi];
                    if (fabs(apq) < 1e-300) continue;
                    double theta = (A[qi][qi] - A[pi][pi]) / (2.0 * apq);
                    double tt = 1.0 / (fabs(theta) + sqrt(theta * theta + 1.0));
                    if (theta < 0.0) tt = -tt;
                    double c = 1.0 / sqrt(tt * tt + 1.0);
                    double s = tt * c;
#pragma unroll
                    for (int k = 0; k < 4; k++) {
                        double akp = A[k][pi], akq = A[k][qi];
                        A[k][pi] = c * akp - s * akq;
                        A[k][qi] = s * akp + c * akq;
                    }
#pragma unroll
                    for (int k = 0; k < 4; k++) {
                        double apk = A[pi][k], aqk = A[qi][k];
                        A[pi][k] = c * apk - s * aqk;
                        A[qi][k] = s * apk + c * aqk;
                    }
#pragma unroll
                    for (int k = 0; k < 4; k++) {
                        double qkp = Q[k][pi], qkq = Q[k][qi];
                        Q[k][pi] = c * qkp - s * qkq;
                        Q[k][qi] = s * qkp + c * qkq;
                    }
                }
        }

        double lam[4], smax = 0.0;
#pragma unroll
        for (int k = 0; k < 4; k++) {
            lam[k] = A[k][k];
            double a = fabs(lam[k]);
            if (a > smax) smax = a;
        }
        double cut = (double)RCOND * smax;

        double acc[4] = {0.0, 0.0, 0.0, 0.0};
#pragma unroll
        for (int k = 0; k < 4; k++) {
            if (fabs(lam[k]) > cut) {
                double w = (Q[0][k]*fd[0] + Q[1][k]*fd[1] +
                            Q[2][k]*fd[2] + Q[3][k]*fd[3]) / lam[k];
#pragma unroll
                for (int j = 0; j < 4; j++)
                    acc[j] += w * Q[j][k];
            }
        }

        out[b] = make_float4((float)acc[0], (float)acc[1],
                             (float)acc[2], (float)acc[3]);
    }

    // last-finishing block resets the counter for the next graph replay
    __syncthreads();
    if (threadIdx.x == 0) {
        unsigned d = atomicAdd(&g_done_blocks, 1u);
        if (d == gridDim.x - 1u) {
            g_slow_count = 0u;
            g_done_blocks = 0u;
        }
    }
}

extern "C" void kernel_launch(void* const* d_in, const int* in_sizes, int n_in,
                              void* d_out, int out_size)
{
    const float* y = (const float*)d_in[0];
    const float* W = (const float*)d_in[1];
    const float* V = (const float*)d_in[2];
    int B = in_sizes[0] / 8;   // y is [B, 8]

    int threads = 256;
    int blocks = (B + threads - 1) / threads;
    rcpl_fast<<<blocks, threads>>>((const float4*)y, W, V, (float4*)d_out, B);
    rcpl_slow<<<64, 128>>>((const float4*)y, W, V, (float4*)d_out);
}

// round 7
// speedup vs baseline: 6.5111x; 4.7375x over previous
#include <cuda_runtime.h>

// Relativistic charged-particle Lagrangian dynamics — single fused kernel.
// H (J_uu) matches the reference's JAX/XLA f32 bits exactly (XLA tanh
// rational approximation, cublas-style fma k-chains, autodiff association
// (0.1*A_j)*A_i, const-folded +eta). Unrouted rows: Cramer with accurate
// 2x2 minors + double-single determinant (bit-proven adequate). Rows whose
// lambda_min could be near the jnp.linalg.pinv cutoff take an in-thread fp64
// path: adjugate-based rank-1 deflation (null direction from the dominant
// adjugate column + one refinement multiply), Rayleigh lambda_min, power-
// iteration sigma_max^2, squared-compare against the cutoff, and exact
// pinv semantics via solution projection. No fp64 div/sqrt anywhere
// (Newton reciprocal from f32 seeds) — B300 fp64 subroutines are ~100us/row.

#define RCOND 4.7683716e-6f   /* 10 * 4 * eps(f32): jnp pinv default */

// ---------- XLA GPU f32 tanh ----------
__device__ __forceinline__ float xla_tanh(float x) {
    float ax = fabsf(x);
    float xc = fminf(fmaxf(x, -7.90531110763549805f), 7.90531110763549805f);
    float x2 = __fmul_rn(xc, xc);
    float np = -2.76076847742355e-16f;
    np = __fmaf_rn(np, x2, 2.00018790482477e-13f);
    np = __fmaf_rn(np, x2, -8.60467152213735e-11f);
    np = __fmaf_rn(np, x2, 5.12229709037114e-08f);
    np = __fmaf_rn(np, x2, 1.48572235717979e-05f);
    np = __fmaf_rn(np, x2, 6.37261928875436e-04f);
    np = __fmaf_rn(np, x2, 4.89352455891786e-03f);
    float num = __fmul_rn(xc, np);
    float dp = 1.19825839466702e-06f;
    dp = __fmaf_rn(dp, x2, 1.18534705686654e-04f);
    dp = __fmaf_rn(dp, x2, 2.26843463243900e-03f);
    dp = __fmaf_rn(dp, x2, 4.89352518554385e-03f);
    float r = __fdiv_rn(num, dp);
    return (ax < 0.0004f) ? x : r;
}

// ---------- double-single helpers ----------
__device__ __forceinline__ void two_sum(float a, float b, float& s, float& e) {
    s = a + b;
    float bb = s - a;
    e = (a - (s - bb)) + (b - bb);
}
__device__ __forceinline__ void two_prod(float a, float b, float& p, float& e) {
    p = a * b;
    e = fmaf(a, b, -p);
}
__device__ __forceinline__ float dif2(float p0, float p1, float q0, float q1) {
    float w = q0 * q1;
    float e = fmaf(q0, q1, -w);
    float r = fmaf(p0, p1, -w);
    return r - e;
}

// ---------- fp64 slow path: exact pinv apply, no fp64 div/sqrt ----------
__device__ __noinline__ float4 solve_pinv64(const float m32[4][4], const float f32a[4])
{
    double M[4][4], F[4];
#pragma unroll
    for (int i = 0; i < 4; i++) {
        F[i] = (double)f32a[i];
#pragma unroll
        for (int j = 0; j < 4; j++)
            M[i][j] = (double)m32[i][j];
    }

    // adjugate + determinant in fp64
    double s0 = M[0][0]*M[1][1] - M[1][0]*M[0][1];
    double s1 = M[0][0]*M[1][2] - M[1][0]*M[0][2];
    double s2 = M[0][0]*M[1][3] - M[1][0]*M[0][3];
    double s3 = M[0][1]*M[1][2] - M[1][1]*M[0][2];
    double s4 = M[0][1]*M[1][3] - M[1][1]*M[0][3];
    double s5 = M[0][2]*M[1][3] - M[1][2]*M[0][3];
    double c5 = M[2][2]*M[3][3] - M[3][2]*M[2][3];
    double c4 = M[2][1]*M[3][3] - M[3][1]*M[2][3];
    double c3 = M[2][1]*M[3][2] - M[3][1]*M[2][2];
    double c2 = M[2][0]*M[3][3] - M[3][0]*M[2][3];
    double c1 = M[2][0]*M[3][2] - M[3][0]*M[2][2];
    double c0 = M[2][0]*M[3][1] - M[3][0]*M[2][1];

    double det = s0*c5 - s1*c4 + s2*c3 + s3*c2 - s4*c1 + s5*c0;

    double adj[4][4];
    adj[0][0] =  M[1][1]*c5 - M[1][2]*c4 + M[1][3]*c3;
    adj[0][1] = -M[0][1]*c5 + M[0][2]*c4 - M[0][3]*c3;
    adj[0][2] =  M[3][1]*s5 - M[3][2]*s4 + M[3][3]*s3;
    adj[0][3] = -M[2][1]*s5 + M[2][2]*s4 - M[2][3]*s3;
    adj[1][0] = -M[1][0]*c5 + M[1][2]*c2 - M[1][3]*c1;
    adj[1][1] =  M[0][0]*c5 - M[0][2]*c2 + M[0][3]*c1;
    adj[1][2] = -M[3][0]*s5 + M[3][2]*s2 - M[3][3]*s1;
    adj[1][3] =  M[2][0]*s5 - M[2][2]*s2 + M[2][3]*s1;
    adj[2][0] =  M[1][0]*c4 - M[1][1]*c2 + M[1][3]*c0;
    adj[2][1] = -M[0][0]*c4 + M[0][1]*c2 - M[0][3]*c0;
    adj[2][2] =  M[3][0]*s4 - M[3][1]*s2 + M[3][3]*s0;
    adj[2][3] = -M[2][0]*s4 + M[2][1]*s2 - M[2][3]*s0;
    adj[3][0] = -M[1][0]*c3 + M[1][1]*c1 - M[1][2]*c0;
    adj[3][1] =  M[0][0]*c3 - M[0][1]*c1 + M[0][2]*c0;
    adj[3][2] = -M[3][0]*s3 + M[3][1]*s1 - M[3][2]*s0;
    adj[3][3] =  M[2][0]*s3 - M[2][1]*s1 + M[2][2]*s0;

    // 1/det: f32 seed + 2 fp64 Newton steps (no fp64 div)
    double rdet = (double)__frcp_rn((float)det);
    rdet = rdet * (2.0 - det * rdet);
    rdet = rdet * (2.0 - det * rdet);

    // acc0 = m^-1 f  (row-vector f times adj, as in the fast path)
    double acc[4];
#pragma unroll
    for (int j = 0; j < 4; j++)
        acc[j] = (F[0]*adj[0][j] + F[1]*adj[1][j]
                + F[2]*adj[2][j] + F[3]*adj[3][j]) * rdet;

    // null-ish direction: dominant adjugate column (adj -> c*v*v^T as lam_min->0)
    double cn[4];
#pragma unroll
    for (int c = 0; c < 4; c++)
        cn[c] = adj[0][c]*adj[0][c] + adj[1][c]*adj[1][c]
              + adj[2][c]*adj[2][c] + adj[3][c]*adj[3][c];
    int cbest = 0;
    if (cn[1] > cn[cbest]) cbest = 1;
    if (cn[2] > cn[cbest]) cbest = 2;
    if (cn[3] > cn[cbest]) cbest = 3;
    double v[4] = {adj[0][cbest], adj[1][cbest], adj[2][cbest], adj[3][cbest]};
    // one refinement multiply: error O((lam_min/lam2)^2)
    double v2[4];
#pragma unroll
    for (int i = 0; i < 4; i++)
        v2[i] = adj[i][0]*v[0] + adj[i][1]*v[1] + adj[i][2]*v[2] + adj[i][3]*v[3];

    // Rayleigh lambda_min (unnormalized): num = v2^T M v2, den = v2^T v2
    double Mv[4];
#pragma unroll
    for (int i = 0; i < 4; i++)
        Mv[i] = M[i][0]*v2[0] + M[i][1]*v2[1] + M[i][2]*v2[2] + M[i][3]*v2[3];
    double num = v2[0]*Mv[0] + v2[1]*Mv[1] + v2[2]*Mv[2] + v2[3]*Mv[3];
    double den = v2[0]*v2[0] + v2[1]*v2[1] + v2[2]*v2[2] + v2[3]*v2[3];

    // sigma_max^2 via power iteration on M^2 (Rayleigh in squares, no sqrt)
    double tn[4];
#pragma unroll
    for (int c = 0; c < 4; c++)
        tn[c] = M[0][c]*M[0][c] + M[1][c]*M[1][c]
              + M[2][c]*M[2][c] + M[3][c]*M[3][c];
    int tbest = 0;
    if (tn[1] > tn[tbest]) tbest = 1;
    if (tn[2] > tn[tbest]) tbest = 2;
    if (tn[3] > tn[tbest]) tbest = 3;
    double t[4] = {M[0][tbest], M[1][tbest], M[2][tbest], M[3][tbest]};
#pragma unroll
    for (int it = 0; it < 6; it++) {
        double tt0 = M[0][0]*t[0] + M[0][1]*t[1] + M[0][2]*t[2] + M[0][3]*t[3];
        double tt1 = M[1][0]*t[0] + M[1][1]*t[1] + M[1][2]*t[2] + M[1][3]*t[3];
        double tt2 = M[2][0]*t[0] + M[2][1]*t[1] + M[2][2]*t[2] + M[2][3]*t[3];
        double tt3 = M[3][0]*t[0] + M[3][1]*t[1] + M[3][2]*t[2] + M[3][3]*t[3];
        t[0] = tt0; t[1] = tt1; t[2] = tt2; t[3] = tt3;
    }
    double z0 = M[0][0]*t[0] + M[0][1]*t[1] + M[0][2]*t[2] + M[0][3]*t[3];
    double z1 = M[1][0]*t[0] + M[1][1]*t[1] + M[1][2]*t[2] + M[1][3]*t[3];
    double z2 = M[2][0]*t[0] + M[2][1]*t[1] + M[2][2]*t[2] + M[2][3]*t[3];
    double z3 = M[3][0]*t[0] + M[3][1]*t[1] + M[3][2]*t[2] + M[3][3]*t[3];
    double zz = z0*z0 + z1*z1 + z2*z2 + z3*z3;
    double tt = t[0]*t[0] + t[1]*t[1] + t[2]*t[2] + t[3]*t[3];
    // sigma_max^2 = zz/tt ; keep iff lam^2 > RCOND^2*sigma_max^2
    // lam = num/den  =>  num^2 * tt > RCOND^2 * zz * den^2
    double R2 = (double)RCOND * (double)RCOND;
    bool keep = (num*num)*tt > R2*zz*(den*den);

    if (!keep) {
        // pinv zeroes the lam_min eigendirection: project it out of the solution
        double rden = (double)__frcp_rn((float)den);
        rden = rden * (2.0 - den * rden);
        rden = rden * (2.0 - den * rden);
        double proj = (v2[0]*acc[0] + v2[1]*acc[1]
                     + v2[2]*acc[2] + v2[3]*acc[3]) * rden;
#pragma unroll
        for (int j = 0; j < 4; j++)
            acc[j] -= proj * v2[j];
    }

    return make_float4((float)acc[0], (float)acc[1], (float)acc[2], (float)acc[3]);
}

// ---------- physics: J_uu (bit-exact vs reference) + force (compact) ----------
__device__ __forceinline__ void compute_mf(const float4* __restrict__ y,
                                           const float*  __restrict__ Wg,
                                           const float*  __restrict__ Vg,
                                           int b, float m[4][4], float force[4])
{
    const float eta[4] = {1.f, -1.f, -1.f, -1.f};
    float4 xv = y[2 * b];
    float4 uv = y[2 * b + 1];
    float x[4] = {xv.x, xv.y, xv.z, xv.w};
    float u[4] = {uv.x, uv.y, uv.z, uv.w};

    float A[4], dk[4];
#pragma unroll
    for (int i = 0; i < 4; i++) {
        float wx = __fmul_rn(Wg[i*4+0], x[0]);
        wx = __fmaf_rn(Wg[i*4+1], x[1], wx);
        wx = __fmaf_rn(Wg[i*4+2], x[2], wx);
        wx = __fmaf_rn(Wg[i*4+3], x[3], wx);
        float vx = __fmul_rn(Vg[i*4+0], x[0]);
        vx = __fmaf_rn(Vg[i*4+1], x[1], vx);
        vx = __fmaf_rn(Vg[i*4+2], x[2], vx);
        vx = __fmaf_rn(Vg[i*4+3], x[3], vx);
        float t = xla_tanh(wx);
        A[i]  = __fadd_rn(t, vx);
        dk[i] = __fsub_rn(1.0f, __fmul_rn(t, t));
    }

    // ---- J_uu: BIT-CRITICAL layout (matches reference autodiff graph) ----
    float oA[4];
#pragma unroll
    for (int j = 0; j < 4; j++)
        oA[j] = __fmul_rn(0.1f, A[j]);
#pragma unroll
    for (int i = 0; i < 4; i++) {
#pragma unroll
        for (int j = 0; j < 4; j++)
            m[i][j] = __fmul_rn(oA[j], A[i]);
        float xx2 = __fmul_rn(__fmul_rn(0.2f, x[i]), x[i]);
        m[i][i] = __fadd_rn(__fadd_rn(m[i][i], xx2), eta[i]);
    }

    // ---- force: compact algebra (rounding not kappa-amplified) ----
    float G[4][4];
#pragma unroll
    for (int k = 0; k < 4; k++)
#pragma unroll
        for (int j = 0; j < 4; j++)
            G[j][k] = fmaf(Wg[k*4+j], dk[k], Vg[k*4+j]);

    float s = u[0]*A[0] + u[1]*A[1] + u[2]*A[2] + u[3]*A[3];
    float tbs = 0.1f * s;

    float g[4], ge[4], h[4];
#pragma unroll
    for (int j = 0; j < 4; j++) {
        g[j]  = G[j][0]*u[0] + G[j][1]*u[1] + G[j][2]*u[2] + G[j][3]*u[3];
        ge[j] = G[j][0]*u[0] - G[j][1]*u[1] - G[j][2]*u[2] - G[j][3]*u[3];
        h[j]  = G[0][j]*u[0] + G[1][j]*u[1] + G[2][j]*u[2] + G[3][j]*u[3];
    }
    float p = h[0]*u[0] + h[1]*u[1] + h[2]*u[2] + h[3]*u[3];

#pragma unroll
    for (int j = 0; j < 4; j++) {
        force[j] = -0.2f * x[j] * u[j] * u[j]
                 + 0.5f * ge[j] + tbs * g[j]
                 - 0.5f * eta[j] * h[j] - tbs * h[j]
                 - 0.1f * p * A[j];
    }
}

// ---------- the one kernel ----------
__global__ void __launch_bounds__(256)
rcpl_kernel(const float4* __restrict__ y,
            const float*  __restrict__ Wg,
            const float*  __restrict__ Vg,
            float4* __restrict__ out,
            int B)
{
    int b = blockIdx.x * blockDim.x + threadIdx.x;
    if (b >= B) return;

    float m[4][4], f[4];
    compute_mf(y, Wg, Vg, b, m, f);

    // accurate 2x2 minors
    float s0 = dif2(m[0][0], m[1][1], m[1][0], m[0][1]);
    float s1 = dif2(m[0][0], m[1][2], m[1][0], m[0][2]);
    float s2 = dif2(m[0][0], m[1][3], m[1][0], m[0][3]);
    float s3 = dif2(m[0][1], m[1][2], m[1][1], m[0][2]);
    float s4 = dif2(m[0][1], m[1][3], m[1][1], m[0][3]);
    float s5 = dif2(m[0][2], m[1][3], m[1][2], m[0][3]);

    float c5 = dif2(m[2][2], m[3][3], m[3][2], m[2][3]);
    float c4 = dif2(m[2][1], m[3][3], m[3][1], m[2][3]);
    float c3 = dif2(m[2][1], m[3][2], m[3][1], m[2][2]);
    float c2 = dif2(m[2][0], m[3][3], m[3][0], m[2][3]);
    float c1 = dif2(m[2][0], m[3][2], m[3][0], m[2][2]);
    float c0 = dif2(m[2][0], m[3][1], m[3][0], m[2][1]);

    // determinant in double-single
    float hi, lo, p, e, t;
    two_prod(s0, c5, hi, lo);
    two_prod(-s1, c4, p, e); two_sum(hi, p, hi, t); lo += t + e;
    two_prod(s2, c3, p, e);  two_sum(hi, p, hi, t); lo += t + e;
    two_prod(s3, c2, p, e);  two_sum(hi, p, hi, t); lo += t + e;
    two_prod(-s4, c1, p, e); two_sum(hi, p, hi, t); lo += t + e;
    two_prod(s5, c0, p, e);  two_sum(hi, p, hi, t); lo += t + e;

    float adj[4][4];
    adj[0][0] =  m[1][1]*c5 - m[1][2]*c4 + m[1][3]*c3;
    adj[0][1] = -m[0][1]*c5 + m[0][2]*c4 - m[0][3]*c3;
    adj[0][2] =  m[3][1]*s5 - m[3][2]*s4 + m[3][3]*s3;
    adj[0][3] = -m[2][1]*s5 + m[2][2]*s4 - m[2][3]*s3;
    adj[1][0] = -m[1][0]*c5 + m[1][2]*c2 - m[1][3]*c1;
    adj[1][1] =  m[0][0]*c5 - m[0][2]*c2 + m[0][3]*c1;
    adj[1][2] = -m[3][0]*s5 + m[3][2]*s2 - m[3][3]*s1;
    adj[1][3] =  m[2][0]*s5 - m[2][2]*s2 + m[2][3]*s1;
    adj[2][0] =  m[1][0]*c4 - m[1][1]*c2 + m[1][3]*c0;
    adj[2][1] = -m[0][0]*c4 + m[0][1]*c2 - m[0][3]*c0;
    adj[2][2] =  m[3][0]*s4 - m[3][1]*s2 + m[3][3]*s0;
    adj[2][3] = -m[2][0]*s4 + m[2][1]*s2 - m[2][3]*s0;
    adj[3][0] = -m[1][0]*c3 + m[1][1]*c1 - m[1][2]*c0;
    adj[3][1] =  m[0][0]*c3 - m[0][1]*c1 + m[0][2]*c0;
    adj[3][2] = -m[3][0]*s3 + m[3][1]*s1 - m[3][2]*s0;
    adj[3][3] =  m[2][0]*s3 - m[2][1]*s1 + m[2][2]*s0;

    // routing: lam_min <= 2|det|/||adj||_F and lam_min needs checking when
    // below ~2*RCOND*sigma_max <= 2*RCOND*||m||_F, so route (with margin 4) iff
    // det^2 < (4*RCOND)^2 * ||m||_F^2 * ||adj||_F^2.
    float sF2 = 0.f, sAdj2 = 0.f;
#pragma unroll
    for (int i = 0; i < 4; i++)
#pragma unroll
        for (int j = 0; j < 4; j++) {
            sF2   = fmaf(m[i][j],   m[i][j],   sF2);
            sAdj2 = fmaf(adj[i][j], adj[i][j], sAdj2);
        }
    float det1 = hi + lo;
    const float CR = 4.0f * RCOND;
    bool routed = det1 * det1 < (CR * CR) * sF2 * sAdj2;

    float4 res;
    if (!routed) {
        float inv = 1.0f / hi;
        inv = fmaf(-lo, inv * inv, inv);   // 1/(hi+lo)
        res.x = (f[0]*adj[0][0] + f[1]*adj[1][0] + f[2]*adj[2][0] + f[3]*adj[3][0]) * inv;
        res.y = (f[0]*adj[0][1] + f[1]*adj[1][1] + f[2]*adj[2][1] + f[3]*adj[3][1]) * inv;
        res.z = (f[0]*adj[0][2] + f[1]*adj[1][2] + f[2]*adj[2][2] + f[3]*adj[3][2]) * inv;
        res.w = (f[0]*adj[0][3] + f[1]*adj[1][3] + f[2]*adj[2][3] + f[3]*adj[3][3]) * inv;
    } else {
        res = solve_pinv64(m, f);
    }

    out[b] = res;
}

extern "C" void kernel_launch(void* const* d_in, const int* in_sizes, int n_in,
                              void* d_out, int out_size)
{
    const float* y = (const float*)d_in[0];
    const float* W = (const float*)d_in[1];
    const float* V = (const float*)d_in[2];
    int B = in_sizes[0] / 8;   // y is [B, 8]

    int threads = 256;
    int blocks = (B + threads - 1) / threads;
    rcpl_kernel<<<blocks, threads>>>((const float4*)y, W, V, (float4*)d_out, B);
}